// round 14
// baseline (speedup 1.0000x reference)
#include <cuda_runtime.h>
#include <cuda_bf16.h>
#include <cstdint>

#define PAD_VAL  -1000.0f
#define ROW      4096
#define NROWS    1024
#define SEGF     1024          // owned floats per segment
#define NSEG     4
#define NCHK     256           // owned 4-float chunks per segment
#define HALO     16            // halo chunks (next 64 floats)
#define RPB      4             // rows per block
#define RAWF     (SEGF + 64)   // 1088 floats per row incl. halo
#define PLANE    (NCHK + HALO) // 272
#define THREADS  256

// out[i] = relu( max_{j=1..64} h[i+j]-j - h[i] ), right-pad -1000.
// Segment-local frame G[t'] = h[t'] - t':
//   out[t'] = relu( max G[t'+1..t'+64] - G[t'] )
// Block = 4 rows x 2 consecutive segments, double-buffered:
//   issue bulk A, issue bulk B (both in flight), wait A, compute A
//   (B's latency hides under A's compute), wait B, compute B.
// Compute per segment identical to the R13 kernel (rel_err 1.76e-5).
__global__ __launch_bounds__(THREADS, 4) void h2i_kernel(
    const float* __restrict__ hf, float* __restrict__ out)
{
    const int t  = threadIdx.x;
    const int rg = blockIdx.x >> 1;             // row group (4 rows)
    const int sp = blockIdx.x & 1;              // segment pair: segs {2sp, 2sp+1}
    const size_t rbase = ((size_t)rg * RPB) * ROW;

    __shared__ alignas(16) float raw[2][RPB][RAWF];
    __shared__ float sM[2][RPB][PLANE];
    __shared__ alignas(8) uint64_t mbar[2];

    uint32_t mb[2];
    #pragma unroll
    for (int s = 0; s < 2; s++)
        asm volatile("{ .reg .u64 x; cvta.to.shared.u64 x, %1; cvt.u32.u64 %0, x; }"
                     : "=r"(mb[s]) : "l"(&mbar[s]));

    if (t == 0) {
        asm volatile("mbarrier.init.shared.b64 [%0], 1;" :: "r"(mb[0]) : "memory");
        asm volatile("mbarrier.init.shared.b64 [%0], 1;" :: "r"(mb[1]) : "memory");
    }
    __syncthreads();

    // ---- issue BOTH segments' bulk copies up front ----
    #pragma unroll
    for (int s = 0; s < 2; s++) {
        const int seg = 2 * sp + s;
        const bool last = (seg == NSEG - 1);
        const uint32_t row_bytes = last ? SEGF * 4u : RAWF * 4u;
        if (t == 0) {
            asm volatile("mbarrier.arrive.expect_tx.shared.b64 _, [%0], %1;"
                         :: "r"(mb[s]), "r"(row_bytes * RPB) : "memory");
            #pragma unroll
            for (int j = 0; j < RPB; j++) {
                uint32_t dst;
                asm volatile("{ .reg .u64 x; cvta.to.shared.u64 x, %1; cvt.u32.u64 %0, x; }"
                             : "=r"(dst) : "l"(&raw[s][j][0]));
                const float* src = hf + rbase + (size_t)j * ROW + (size_t)seg * SEGF;
                asm volatile(
                    "cp.async.bulk.shared::cta.global.mbarrier::complete_tx::bytes "
                    "[%0], [%1], %2, [%3];"
                    :: "r"(dst), "l"(src), "r"(row_bytes), "r"(mb[s]) : "memory");
            }
        }
        if (last) {                              // sentinel halo (last segment only)
            const int j = t >> 6, idx = t & 63;
            raw[s][j][SEGF + idx] = PAD_VAL;
        }
    }

    const float tb = (float)(4 * t);

    // ---- process segment s = 0 then 1 ----
    #pragma unroll
    for (int s = 0; s < 2; s++) {
        const int seg = 2 * sp + s;
        const size_t obase = rbase + (size_t)seg * SEGF;

        // wait for this buffer's bulk copy (phase 0; each barrier used once)
        {
            uint32_t done;
            asm volatile(
                "{\n\t.reg .pred p;\n\t"
                "mbarrier.try_wait.parity.acquire.cta.shared::cta.b64 p, [%1], 0;\n\t"
                "selp.b32 %0, 1, 0, p;\n\t}"
                : "=r"(done) : "r"(mb[s]) : "memory");
            while (!done) {
                asm volatile(
                    "{\n\t.reg .pred p;\n\t"
                    "mbarrier.try_wait.parity.acquire.cta.shared::cta.b64 p, [%1], 0, 0x989680;\n\t"
                    "selp.b32 %0, 1, 0, p;\n\t}"
                    : "=r"(done) : "r"(mb[s]) : "memory");
            }
        }
        __syncthreads();                         // all lanes past wait (+ halo fill)

        // own chunk -> G-frame, chunk-max plane
        float g[RPB][4];
        #pragma unroll
        for (int j = 0; j < RPB; j++) {
            float4 a = ((const float4*)&raw[s][j][0])[t];
            g[j][0] = a.x - tb;
            g[j][1] = a.y - (tb + 1.0f);
            g[j][2] = a.z - (tb + 2.0f);
            g[j][3] = a.w - (tb + 3.0f);
            sM[s][j][t] = fmaxf(fmaxf(g[j][0], g[j][1]), fmaxf(g[j][2], g[j][3]));
        }
        if (t < 64) {                            // halo chunk maxes
            const int j2 = t >> 4, ht = t & 15;
            float4 a = ((const float4*)&raw[s][j2][0])[NCHK + ht];
            const float hb = (float)(SEGF + 4 * ht);
            sM[s][j2][NCHK + ht] =
                fmaxf(fmaxf(a.x - hb,          a.y - (hb + 1.0f)),
                      fmaxf(a.z - (hb + 2.0f), a.w - (hb + 3.0f)));
        }
        __syncthreads();

        // combine + store
        #pragma unroll
        for (int j = 0; j < RPB; j++) {
            float mid = sM[s][j][t + 1];
            #pragma unroll
            for (int k = 2; k <= 15; k++)
                mid = fmaxf(mid, sM[s][j][t + k]);

            float4 b = ((const float4*)&raw[s][j][0])[t + 16];
            const float bb = tb + 64.0f;
            const float B0 = b.x - bb;
            const float B1 = fmaxf(B0, b.y - (bb + 1.0f));
            const float B2 = fmaxf(B1, b.z - (bb + 2.0f));
            const float B3 = fmaxf(B2, b.w - (bb + 3.0f));

            const float suf2 = g[j][3];
            const float suf1 = fmaxf(g[j][2], suf2);
            const float suf0 = fmaxf(g[j][1], suf1);

            float w, r0, r1, r2, r3;
            w = fmaxf(fmaxf(suf0, mid), B0); r0 = fmaxf(w - g[j][0], 0.0f);
            w = fmaxf(fmaxf(suf1, mid), B1); r1 = fmaxf(w - g[j][1], 0.0f);
            w = fmaxf(fmaxf(suf2, mid), B2); r2 = fmaxf(w - g[j][2], 0.0f);
            w = fmaxf(mid, B3);              r3 = fmaxf(w - g[j][3], 0.0f);

            ((float4*)(out + obase + (size_t)j * ROW))[t] =
                make_float4(r0, r1, r2, r3);
        }
    }
}

extern "C" void kernel_launch(void* const* d_in, const int* in_sizes, int n_in,
                              void* d_out, int out_size)
{
    const float* hf  = (const float*)d_in[0];
    float*       out = (float*)d_out;
    (void)in_sizes; (void)n_in; (void)out_size;
    cudaFuncSetAttribute(h2i_kernel,
                         cudaFuncAttributePreferredSharedMemoryCarveout,
                         cudaSharedmemCarveoutMaxShared);
    // 256 row-groups x 2 segment-pairs = 512 blocks; 4/SM -> single wave (592)
    h2i_kernel<<<(NROWS / RPB) * 2, THREADS>>>(hf, out);
}

// round 15
// speedup vs baseline: 1.0269x; 1.0269x over previous
#include <cuda_runtime.h>
#include <cuda_bf16.h>
#include <cstdint>

#define PAD_VAL  -1000.0f
#define ROW      4096
#define NROWS    1024
#define SEGF     1024          // owned floats per segment
#define NSEG     4
#define NCHK     256           // owned 4-float chunks per segment
#define HALO     16            // halo chunks (next 64 floats)
#define RPB      4             // rows per block: 0-1 via LDG, 2-3 via TMA bulk
#define RAWF     (SEGF + 64)   // 1088 floats per row incl. halo
#define PLANE    (NCHK + HALO) // 272
#define THREADS  256

// out[i] = relu( max_{j=1..64} h[i+j]-j - h[i] ), right-pad -1000.
// Segment-local frame G[t'] = h[t'] - t':
//   out[t'] = relu( max G[t'+1..t'+64] - G[t'] )
// Hybrid read path: rows 2-3 via cp.async.bulk (TMA queue) into smem while
// rows 0-1 stream via LDG.128 (LSU queue) -> registers -> STS. Both engines'
// reads are in flight simultaneously; compute (identical to the R13 kernel)
// starts after one mbarrier wait + one barrier.
__global__ __launch_bounds__(THREADS, 7) void h2i_kernel(
    const float* __restrict__ hf, float* __restrict__ out)
{
    const int t   = threadIdx.x;
    const int rg  = blockIdx.x >> 2;
    const int seg = blockIdx.x & (NSEG - 1);
    const size_t base0 = ((size_t)rg * RPB) * ROW + (size_t)seg * SEGF;
    const bool last = (seg == NSEG - 1);

    __shared__ alignas(16) float raw[RPB][RAWF];
    __shared__ float sM[RPB][PLANE];
    __shared__ alignas(8) uint64_t mbar;

    uint32_t mbar_a;
    asm volatile("{ .reg .u64 x; cvta.to.shared.u64 x, %1; cvt.u32.u64 %0, x; }"
                 : "=r"(mbar_a) : "l"(&mbar));

    if (t == 0)
        asm volatile("mbarrier.init.shared.b64 [%0], 1;" :: "r"(mbar_a) : "memory");
    __syncthreads();

    // ---- TMA queue: rows 2-3 (issued first so both engines run together) ----
    const uint32_t row_bytes = last ? SEGF * 4u : RAWF * 4u;
    if (t == 0) {
        asm volatile("mbarrier.arrive.expect_tx.shared.b64 _, [%0], %1;"
                     :: "r"(mbar_a), "r"(row_bytes * 2u) : "memory");
        #pragma unroll
        for (int j = 2; j < 4; j++) {
            uint32_t dst;
            asm volatile("{ .reg .u64 x; cvta.to.shared.u64 x, %1; cvt.u32.u64 %0, x; }"
                         : "=r"(dst) : "l"(&raw[j][0]));
            const float* src = hf + base0 + (size_t)j * ROW;
            asm volatile(
                "cp.async.bulk.shared::cta.global.mbarrier::complete_tx::bytes "
                "[%0], [%1], %2, [%3];"
                :: "r"(dst), "l"(src), "r"(row_bytes), "r"(mbar_a) : "memory");
        }
    }

    const float tb = (float)(4 * t);

    // ---- LSU queue: rows 0-1 via LDG.128 -> sM inline + STS to raw ----
    #pragma unroll
    for (int j = 0; j < 2; j++) {
        float4 a = ((const float4*)(hf + base0 + (size_t)j * ROW))[t];
        ((float4*)&raw[j][0])[t] = a;
        sM[j][t] = fmaxf(fmaxf(a.x - tb,          a.y - (tb + 1.0f)),
                         fmaxf(a.z - (tb + 2.0f), a.w - (tb + 3.0f)));
    }
    if (t < 32) {                                // halo chunks of rows 0-1
        const int j = t >> 4, ht = t & 15;
        float4 a;
        if (!last)
            a = ((const float4*)(hf + base0 + (size_t)j * ROW + SEGF))[ht];
        else
            a = make_float4(PAD_VAL, PAD_VAL, PAD_VAL, PAD_VAL);
        ((float4*)&raw[j][SEGF])[ht] = a;
        const float hb = (float)(SEGF + 4 * ht);
        sM[j][NCHK + ht] = fmaxf(fmaxf(a.x - hb,          a.y - (hb + 1.0f)),
                                 fmaxf(a.z - (hb + 2.0f), a.w - (hb + 3.0f)));
    }
    // sentinel halo for TMA rows on the last segment (copied region excludes it)
    if (last && t >= 32 && t < 160) {            // 128 floats
        const int u = t - 32;
        raw[2 + (u >> 6)][SEGF + (u & 63)] = PAD_VAL;
    }

    // ---- wait for TMA rows (acquire), then order ALL smem writes ----
    {
        uint32_t done;
        asm volatile(
            "{\n\t.reg .pred p;\n\t"
            "mbarrier.try_wait.parity.acquire.cta.shared::cta.b64 p, [%1], 0;\n\t"
            "selp.b32 %0, 1, 0, p;\n\t}"
            : "=r"(done) : "r"(mbar_a) : "memory");
        while (!done) {
            asm volatile(
                "{\n\t.reg .pred p;\n\t"
                "mbarrier.try_wait.parity.acquire.cta.shared::cta.b64 p, [%1], 0, 0x989680;\n\t"
                "selp.b32 %0, 1, 0, p;\n\t}"
                : "=r"(done) : "r"(mbar_a) : "memory");
        }
    }
    __syncthreads();

    // ---- chunk-max planes for TMA rows (from smem) ----
    #pragma unroll
    for (int j = 2; j < 4; j++) {
        float4 a = ((const float4*)&raw[j][0])[t];
        sM[j][t] = fmaxf(fmaxf(a.x - tb,          a.y - (tb + 1.0f)),
                         fmaxf(a.z - (tb + 2.0f), a.w - (tb + 3.0f)));
    }
    if (t < 32) {
        const int j2 = 2 + (t >> 4), ht = t & 15;
        float4 a = ((const float4*)&raw[j2][SEGF])[ht];
        const float hb = (float)(SEGF + 4 * ht);
        sM[j2][NCHK + ht] = fmaxf(fmaxf(a.x - hb,          a.y - (hb + 1.0f)),
                                  fmaxf(a.z - (hb + 2.0f), a.w - (hb + 3.0f)));
    }
    __syncthreads();

    // ---- combine + store (identical math to R13; rel_err 1.76e-5) ----
    #pragma unroll
    for (int j = 0; j < RPB; j++) {
        float4 a = ((const float4*)&raw[j][0])[t];
        const float g0 = a.x - tb;
        const float g1 = a.y - (tb + 1.0f);
        const float g2 = a.z - (tb + 2.0f);
        const float g3 = a.w - (tb + 3.0f);

        float mid = sM[j][t + 1];
        #pragma unroll
        for (int k = 2; k <= 15; k++)
            mid = fmaxf(mid, sM[j][t + k]);

        float4 b = ((const float4*)&raw[j][0])[t + 16];
        const float bb = tb + 64.0f;
        const float B0 = b.x - bb;
        const float B1 = fmaxf(B0, b.y - (bb + 1.0f));
        const float B2 = fmaxf(B1, b.z - (bb + 2.0f));
        const float B3 = fmaxf(B2, b.w - (bb + 3.0f));

        const float suf2 = g3;
        const float suf1 = fmaxf(g2, suf2);
        const float suf0 = fmaxf(g1, suf1);

        float w, r0, r1, r2, r3;
        w = fmaxf(fmaxf(suf0, mid), B0); r0 = fmaxf(w - g0, 0.0f);
        w = fmaxf(fmaxf(suf1, mid), B1); r1 = fmaxf(w - g1, 0.0f);
        w = fmaxf(fmaxf(suf2, mid), B2); r2 = fmaxf(w - g2, 0.0f);
        w = fmaxf(mid, B3);              r3 = fmaxf(w - g3, 0.0f);

        ((float4*)(out + base0 + (size_t)j * ROW))[t] = make_float4(r0, r1, r2, r3);
    }
}

extern "C" void kernel_launch(void* const* d_in, const int* in_sizes, int n_in,
                              void* d_out, int out_size)
{
    const float* hf  = (const float*)d_in[0];
    float*       out = (float*)d_out;
    (void)in_sizes; (void)n_in; (void)out_size;
    cudaFuncSetAttribute(h2i_kernel,
                         cudaFuncAttributePreferredSharedMemoryCarveout,
                         cudaSharedmemCarveoutMaxShared);
    // 256 row-groups x 4 segments = 1024 blocks; 7/SM -> single wave
    h2i_kernel<<<(NROWS / RPB) * NSEG, THREADS>>>(hf, out);
}